// round 5
// baseline (speedup 1.0000x reference)
#include <cuda_runtime.h>

// ---------------------------------------------------------------------------
// Contrast loss:
//   zp1 = proj(z_mp), zp2 = proj(z_sc)   (8->8 MLP with ELU, shared weights)
//   m[i][j] = exp( cos(zp1_i, zp2_j) / tau )
//   loss = LAM*mean(log(rowsum/ m_ii^-1 ...))  ==
//          LAM*mean(log rs) + (1-LAM)*mean(log cs) - mean(log m_ii)
// where rs_i = sum_j m[i][j] + EPS, cs_j = sum_i m[i][j] + EPS,
// and log(m_ii) = logit_ii (no exp/log needed).
//
// Strategy:
//  K1 proj:      a_i = zp1_i/|zp1_i| * (log2e/tau),  b_j = zp2_j/|zp2_j|
//                so dot(a_i,b_j) = log2(m[i][j]); pads zero rows; inits sums.
//  K2 pairwise:  single pass over all N*N pairs. CTA = 64 rows x 1 col-chunk.
//                Thread (rg,cg): 4 rows (registers) x 4 cols per step.
//                e = ex2.approx(dot8_f32x2) -> rowacc regs + shfl-reduced
//                column sums (atomicAdd). Zero-padded rows/cols contribute
//                exactly 1.0 each; cancelled exactly via sum init offsets.
//  K3 final:     one CTA: mean(log rs) / mean(log cs) / mean(diag logits).
// ---------------------------------------------------------------------------

#define TAU   0.5f
#define LAM   0.5f
#define EPS   1e-8f
#define LOG2E 1.4426950408889634f
#define LN2   0.6931471805599453f

#define MAXPAD 16384

__device__ __align__(16) float g_a[MAXPAD * 8];
__device__ __align__(16) float g_b[MAXPAD * 8];
__device__ float g_rs[MAXPAD];
__device__ float g_cs[MAXPAD];

typedef unsigned long long u64;

// packed f32x2 dot over 8 floats (4 x b64 operands), returns scalar sum
__device__ __forceinline__ float dot8(const u64* a, const u64* b) {
    u64 acc;
    asm("mul.rn.f32x2 %0, %1, %2;"     : "=l"(acc) : "l"(a[0]), "l"(b[0]));
    asm("fma.rn.f32x2 %0, %1, %2, %3;" : "=l"(acc) : "l"(a[1]), "l"(b[1]), "l"(acc));
    asm("fma.rn.f32x2 %0, %1, %2, %3;" : "=l"(acc) : "l"(a[2]), "l"(b[2]), "l"(acc));
    asm("fma.rn.f32x2 %0, %1, %2, %3;" : "=l"(acc) : "l"(a[3]), "l"(b[3]), "l"(acc));
    float lo, hi;
    asm("mov.b64 {%0, %1}, %2;" : "=f"(lo), "=f"(hi) : "l"(acc));
    return lo + hi;
}

__device__ __forceinline__ float ex2(float x) {
    float r;
    asm("ex2.approx.ftz.f32 %0, %1;" : "=f"(r) : "f"(x));
    return r;
}

// ------------------------------- K1: projection ----------------------------
__global__ void proj_kernel(const float* __restrict__ z_mp,
                            const float* __restrict__ z_sc,
                            const float* __restrict__ W1,
                            const float* __restrict__ b1,
                            const float* __restrict__ W2,
                            const float* __restrict__ b2,
                            int N, int NpadC, float rs_init, float cs_init) {
    __shared__ float w1s[64], w2s[64], b1s[8], b2s[8];
    int t = threadIdx.x;
    if (t < 64) { w1s[t] = W1[t]; w2s[t] = W2[t]; }
    if (t < 8)  { b1s[t] = b1[t]; b2s[t] = b2[t]; }
    __syncthreads();

    int idx = blockIdx.x * blockDim.x + t;
    if (idx >= 2 * NpadC) return;
    int side = (idx >= NpadC) ? 1 : 0;     // 0 = z_mp -> g_a, 1 = z_sc -> g_b
    int row  = side ? (idx - NpadC) : idx;
    float* dst = side ? g_b : g_a;

    if (!side) { g_rs[row] = rs_init; g_cs[row] = cs_init; }

    if (row >= N) {
#pragma unroll
        for (int k = 0; k < 8; k++) dst[row * 8 + k] = 0.0f;
        return;
    }

    const float* z = (side ? z_sc : z_mp) + row * 8;
    float zr[8];
#pragma unroll
    for (int d = 0; d < 8; d++) zr[d] = z[d];

    float h[8];
#pragma unroll
    for (int k = 0; k < 8; k++) {
        float s = b1s[k];
#pragma unroll
        for (int d = 0; d < 8; d++) s = fmaf(zr[d], w1s[k * 8 + d], s);
        h[k] = (s > 0.0f) ? s : (expf(s) - 1.0f);   // ELU(alpha=1)
    }
    float o[8];
    float nn = 0.0f;
#pragma unroll
    for (int j = 0; j < 8; j++) {
        float s = b2s[j];
#pragma unroll
        for (int k = 0; k < 8; k++) s = fmaf(h[k], w2s[j * 8 + k], s);
        o[j] = s;
        nn = fmaf(s, s, nn);
    }
    float scl = (side ? 1.0f : (LOG2E / TAU)) * rsqrtf(nn);
#pragma unroll
    for (int k = 0; k < 8; k++) dst[row * 8 + k] = o[k] * scl;
}

// ------------------------------- K2: pairwise ------------------------------
// grid: (nRowBlocks, NCHUNKS). CTA: 256 threads.
// rg = tid & 15 (row group, intra-warp), cg = tid >> 4 (col group).
// Thread owns rows row0..row0+3 (registers), iterates 4-col groups stride 64.
__global__ __launch_bounds__(256, 2) void pair_kernel(int nsteps) {
    const int rg = threadIdx.x & 15;
    const int cg = threadIdx.x >> 4;
    const int row0  = blockIdx.x * 64 + rg * 4;
    const int cbase = blockIdx.y * (nsteps * 64) + cg * 4;

    const ulonglong2* ga = reinterpret_cast<const ulonglong2*>(g_a);
    const ulonglong2* gb = reinterpret_cast<const ulonglong2*>(g_b);

    u64 a[4][4];
#pragma unroll
    for (int r = 0; r < 4; r++) {
        ulonglong2 p0 = ga[(row0 + r) * 2];
        ulonglong2 p1 = ga[(row0 + r) * 2 + 1];
        a[r][0] = p0.x; a[r][1] = p0.y; a[r][2] = p1.x; a[r][3] = p1.y;
    }

    float rowacc[4] = {0.f, 0.f, 0.f, 0.f};

    for (int ts = 0; ts < nsteps; ++ts) {
        const int j0 = cbase + ts * 64;
        u64 b[4][4];
#pragma unroll
        for (int c = 0; c < 4; c++) {
            ulonglong2 p0 = gb[(j0 + c) * 2];
            ulonglong2 p1 = gb[(j0 + c) * 2 + 1];
            b[c][0] = p0.x; b[c][1] = p0.y; b[c][2] = p1.x; b[c][3] = p1.y;
        }
#pragma unroll
        for (int c = 0; c < 4; c++) {
            float cacc = 0.0f;
#pragma unroll
            for (int r = 0; r < 4; r++) {
                float e = ex2(dot8(a[r], b[c]));
                rowacc[r] += e;
                cacc += e;
            }
            // reduce column partial over the 16 row-groups (intra-half-warp)
            cacc += __shfl_xor_sync(0xffffffffu, cacc, 1);
            cacc += __shfl_xor_sync(0xffffffffu, cacc, 2);
            cacc += __shfl_xor_sync(0xffffffffu, cacc, 4);
            cacc += __shfl_xor_sync(0xffffffffu, cacc, 8);
            if (rg == 0) atomicAdd(&g_cs[j0 + c], cacc);
        }
    }

    // reduce row partials over the 16 col-groups (cross-warp, once per CTA)
    __shared__ float red[64][17];
#pragma unroll
    for (int r = 0; r < 4; r++) red[rg * 4 + r][cg] = rowacc[r];
    __syncthreads();
    if (threadIdx.x < 64) {
        float s = 0.0f;
#pragma unroll
        for (int q = 0; q < 16; q++) s += red[threadIdx.x][q];
        atomicAdd(&g_rs[blockIdx.x * 64 + threadIdx.x], s);
    }
}

// ------------------------------- K3: final ---------------------------------
__global__ void final_kernel(float* __restrict__ out, int N) {
    __shared__ float sh0[256], sh1[256], sh2[256];
    const int t = threadIdx.x;
    float lr = 0.f, lc = 0.f, dd = 0.f;
    for (int i = t; i < N; i += 256) {
        lr += logf(g_rs[i]);
        lc += logf(g_cs[i]);
        const float* a = g_a + i * 8;
        const float* b = g_b + i * 8;
        float d = 0.f;
#pragma unroll
        for (int k = 0; k < 8; k++) d = fmaf(a[k], b[k], d);
        dd += d;  // log2-domain logit; natural log = d * ln2
    }
    sh0[t] = lr; sh1[t] = lc; sh2[t] = dd;
    __syncthreads();
    for (int s = 128; s > 0; s >>= 1) {
        if (t < s) { sh0[t] += sh0[t + s]; sh1[t] += sh1[t + s]; sh2[t] += sh2[t + s]; }
        __syncthreads();
    }
    if (t == 0) {
        out[0] = (LAM * sh0[0] + (1.0f - LAM) * sh1[0] - LN2 * sh2[0]) / (float)N;
    }
}

// ------------------------------- launch -------------------------------------
extern "C" void kernel_launch(void* const* d_in, const int* in_sizes, int n_in,
                              void* d_out, int out_size) {
    const float* z_mp = (const float*)d_in[0];
    const float* z_sc = (const float*)d_in[1];
    const float* W1   = (const float*)d_in[2];
    const float* b1   = (const float*)d_in[3];
    const float* W2   = (const float*)d_in[4];
    const float* b2   = (const float*)d_in[5];
    float* out = (float*)d_out;

    const int N = in_sizes[0] / 8;

    const int NCHUNKS = 4;
    const int RB = (N + 63) / 64;                          // row blocks
    const int colsPerChunk = ((N + NCHUNKS * 64 - 1) / (NCHUNKS * 64)) * 64;
    const int NpadC = NCHUNKS * colsPerChunk;              // padded columns
    const int NpadR = RB * 64;                             // padded rows
    // padded (zero) vectors contribute ex2(0)=1 per pair -> cancel exactly
    const float rs_init = EPS - (float)(NpadC - N);
    const float cs_init = EPS - (float)(NpadR - N);

    const int pthreads = 2 * NpadC;
    proj_kernel<<<(pthreads + 255) / 256, 256>>>(z_mp, z_sc, W1, b1, W2, b2,
                                                 N, NpadC, rs_init, cs_init);

    dim3 grid(RB, NCHUNKS);
    pair_kernel<<<grid, 256>>>(colsPerChunk / 64);

    final_kernel<<<1, 256>>>(out, N);
}